// round 4
// baseline (speedup 1.0000x reference)
#include <cuda_runtime.h>

// MatrixMemory fused persistent kernel (R4):
//   y = state @ query  (per-batch GEMV),  dM = d_out ⊗ key (per-batch outer)
// Persistent grid-stride (1184 CTAs = 148 SM x 8) removes ~14 wave transitions.
// Vectors read via __ldg (L1/L2-resident, no smem sync in the loop).

#define B_  2048
#define DK_ 256
#define DV_ 256
#define TILES (B_ * 8)          // 8 tiles per batch, 32 rows per tile
#define GRID_ (148 * 8)

__global__ __launch_bounds__(256, 8)
void mm_pers_kernel(const float4* __restrict__ state,   // [B, DV, DK] as float4
                    const float4* __restrict__ query,   // [B, DK] as float4
                    const float4* __restrict__ keyv,    // [B, DK] as float4
                    const float*  __restrict__ dout,    // [B, DV]
                    float4*       __restrict__ y,       // [B, DV] as float4
                    float4*       __restrict__ dM)      // [B, DV, DK] as float4
{
    const int tid  = threadIdx.x;
    const int w    = tid >> 5;
    const int lane = tid & 31;

    for (int t = blockIdx.x; t < TILES; t += GRID_) {
        const int b  = t >> 3;
        const int rb = (t & 7) << 5;                    // 32 rows per tile
        const long row0 = (long)b * DV_ + rb + w * 4;   // 4 rows per warp

        const float4* p = state + row0 * (DK_ / 4);

        // ---- front-batch 8 independent streaming loads (4 rows x 2 x 16B) ----
        float4 a[8];
        #pragma unroll
        for (int j = 0; j < 4; j++) {
            a[2*j]   = __ldcs(p + j * 64 + lane);
            a[2*j+1] = __ldcs(p + j * 64 + 32 + lane);
        }

        // vectors: 1KB each per batch, L1/L2 resident (reused by 8 tiles)
        const float4 q0 = __ldg(query + b * 64 + lane);
        const float4 q1 = __ldg(query + b * 64 + 32 + lane);
        const float4 k0 = __ldg(keyv  + b * 64 + lane);
        const float4 k1 = __ldg(keyv  + b * 64 + 32 + lane);

        float dv[4];
        #pragma unroll
        for (int j = 0; j < 4; j++) dv[j] = __ldg(dout + row0 + j);

        float4* pd = dM + row0 * (DK_ / 4);
        float yv[4];

        #pragma unroll
        for (int j = 0; j < 4; j++) {
            // outer-product row write (independent of the loads -> issues early)
            const float d = dv[j];
            float4 o0 = make_float4(d * k0.x, d * k0.y, d * k0.z, d * k0.w);
            float4 o1 = make_float4(d * k1.x, d * k1.y, d * k1.z, d * k1.w);
            __stcs(pd + j * 64 + lane,      o0);
            __stcs(pd + j * 64 + 32 + lane, o1);

            // dot-product partial + warp reduce
            float s = a[2*j].x   * q0.x + a[2*j].y   * q0.y
                    + a[2*j].z   * q0.z + a[2*j].w   * q0.w
                    + a[2*j+1].x * q1.x + a[2*j+1].y * q1.y
                    + a[2*j+1].z * q1.z + a[2*j+1].w * q1.w;
            #pragma unroll
            for (int off = 16; off > 0; off >>= 1)
                s += __shfl_xor_sync(0xFFFFFFFFu, s, off);
            yv[j] = s;                                  // valid in lane 0
        }

        // one aligned 16B y-store per warp (rows row0..row0+3)
        if (lane == 0)
            y[row0 >> 2] = make_float4(yv[0], yv[1], yv[2], yv[3]);
    }
}

extern "C" void kernel_launch(void* const* d_in, const int* in_sizes, int n_in,
                              void* d_out, int out_size)
{
    const float4* state = (const float4*)d_in[0];
    const float4* query = (const float4*)d_in[1];
    const float4* keyv  = (const float4*)d_in[2];
    const float*  dov   = (const float*) d_in[3];

    float* out = (float*)d_out;
    float4* y  = (float4*)out;                     // [B, DV]
    float4* dM = (float4*)(out + (long)B_ * DV_);  // [B, DV, DK]

    mm_pers_kernel<<<GRID_, 256>>>(state, query, keyv, dov, y, dM);
}

// round 5
// speedup vs baseline: 1.3740x; 1.3740x over previous
#include <cuda_runtime.h>

// MatrixMemory fused (R5): R3 tile shape, zero barriers.
//   y = state @ query (per-batch GEMV), dM = d_out ⊗ key (per-batch outer)
// 16384 blocks x 256 threads; warp = 4 rows; 8 front-batched LDG.128 +
// 8 STG.128 per thread; q/k via __ldg (L2-resident, 8-tile reuse);
// y written as one STG.128 per warp from lane 0. No smem, no __syncthreads.

#define B_  2048
#define DK_ 256
#define DV_ 256

__global__ __launch_bounds__(256, 8)
void mm_fused5_kernel(const float4* __restrict__ state,   // [B, DV, DK] as float4
                      const float4* __restrict__ query,   // [B, DK] as float4
                      const float4* __restrict__ keyv,    // [B, DK] as float4
                      const float*  __restrict__ dout,    // [B, DV]
                      float4*       __restrict__ y,       // [B, DV] as float4
                      float4*       __restrict__ dM)      // [B, DV, DK] as float4
{
    const int b  = blockIdx.x >> 3;            // 8 blocks per batch
    const int rb = (blockIdx.x & 7) << 5;      // 32 v-rows per block

    const int tid  = threadIdx.x;
    const int w    = tid >> 5;
    const int lane = tid & 31;
    const long row0 = (long)b * DV_ + rb + w * 4;   // 4 rows per warp

    const float4* p = state + row0 * (DK_ / 4);

    // ---- front-batch 8 independent streaming loads (4 rows x 2 x 16B) ----
    float4 a[8];
    #pragma unroll
    for (int j = 0; j < 4; j++) {
        a[2*j]   = __ldcs(p + j * 64 + lane);
        a[2*j+1] = __ldcs(p + j * 64 + 32 + lane);
    }

    // vectors: 1KB per batch, L2-resident (reused by 8 blocks)
    const float4 q0 = __ldg(query + b * 64 + lane);
    const float4 q1 = __ldg(query + b * 64 + 32 + lane);
    const float4 k0 = __ldg(keyv  + b * 64 + lane);
    const float4 k1 = __ldg(keyv  + b * 64 + 32 + lane);

    float dv[4];
    #pragma unroll
    for (int j = 0; j < 4; j++) dv[j] = __ldg(dout + row0 + j);

    float4* pd = dM + row0 * (DK_ / 4);
    float yv[4];

    #pragma unroll
    for (int j = 0; j < 4; j++) {
        // outer-product row write (depends only on k/dv -> issues early)
        const float d = dv[j];
        float4 o0 = make_float4(d * k0.x, d * k0.y, d * k0.z, d * k0.w);
        float4 o1 = make_float4(d * k1.x, d * k1.y, d * k1.z, d * k1.w);
        __stcs(pd + j * 64 + lane,      o0);
        __stcs(pd + j * 64 + 32 + lane, o1);

        // dot-product partial + warp reduce
        float s = a[2*j].x   * q0.x + a[2*j].y   * q0.y
                + a[2*j].z   * q0.z + a[2*j].w   * q0.w
                + a[2*j+1].x * q1.x + a[2*j+1].y * q1.y
                + a[2*j+1].z * q1.z + a[2*j+1].w * q1.w;
        #pragma unroll
        for (int off = 16; off > 0; off >>= 1)
            s += __shfl_xor_sync(0xFFFFFFFFu, s, off);
        yv[j] = s;                                  // valid in lane 0
    }

    // one aligned 16B y-store per warp (rows row0..row0+3)
    if (lane == 0)
        y[row0 >> 2] = make_float4(yv[0], yv[1], yv[2], yv[3]);
}

extern "C" void kernel_launch(void* const* d_in, const int* in_sizes, int n_in,
                              void* d_out, int out_size)
{
    const float4* state = (const float4*)d_in[0];
    const float4* query = (const float4*)d_in[1];
    const float4* keyv  = (const float4*)d_in[2];
    const float*  dov   = (const float*) d_in[3];

    float* out = (float*)d_out;
    float4* y  = (float4*)out;                     // [B, DV]
    float4* dM = (float4*)(out + (long)B_ * DV_);  // [B, DV, DK]

    dim3 grid(B_ * 8);   // 8 blocks/batch, 8 warps, 4 rows/warp
    dim3 block(256);
    mm_fused5_kernel<<<grid, block>>>(state, query, keyv, dov, y, dM);
}